// round 1
// baseline (speedup 1.0000x reference)
#include <cuda_runtime.h>

// RelativePosition: out[b, k(i,j)] = a[b,j] - a[b,i] for j > i, row-major
// over (i,j) strict upper triangle. B=128, N=1024 (derived dynamically).
//
// Row i (i in [0, n-2]) of the triangle is a CONTIGUOUS output segment:
//   base(i) = i*(n-1) - i*(i-1)/2, length L(i) = n-1-i
//   out[b, base(i)+t] = a[b, i+1+t] - a[b, i]
// Pair rows (g, n-2-g): lengths sum to exactly n -> balanced blocks.

__global__ void __launch_bounds__(256)
relpos_kernel(const float* __restrict__ in, float* __restrict__ out,
              int n, int G, long long P)
{
    int b = blockIdx.x / G;
    int g = blockIdx.x - b * G;

    const float* __restrict__ arow = in + (long long)b * n;
    float* __restrict__ outb = out + (long long)b * P;

    int i1 = g;
    int i2 = n - 2 - g;

    #pragma unroll
    for (int r = 0; r < 2; ++r) {
        int i = (r == 0) ? i1 : i2;
        if (r == 1 && i2 == i1) break;   // middle row handled once

        long long base = (long long)i * (n - 1) - (long long)i * (i - 1) / 2;
        int len = n - 1 - i;
        float ai = arow[i];

        // contiguous coalesced load (cached in L1/L2) + coalesced store
        for (int t = threadIdx.x; t < len; t += 256) {
            outb[base + t] = arow[i + 1 + t] - ai;
        }
    }
}

extern "C" void kernel_launch(void* const* d_in, const int* in_sizes, int n_in,
                              void* d_out, int out_size)
{
    const float* in = (const float*)d_in[0];
    float* out = (float*)d_out;

    long long total_in = in_sizes[0];              // B * n
    // out_size = B * n*(n-1)/2  =>  n = 2*out_size/total_in + 1
    int n = (int)(2LL * (long long)out_size / total_in + 1);
    int B = (int)(total_in / n);
    long long P = (long long)n * (n - 1) / 2;      // per-batch output length

    int G = n / 2;                                 // row-pair groups (n even: 512)

    relpos_kernel<<<B * G, 256>>>(in, out, n, G, P);
}

// round 2
// speedup vs baseline: 1.1227x; 1.1227x over previous
#include <cuda_runtime.h>

// RelativePosition: out[b, k(i,j)] = a[b,j] - a[b,i] for j > i, row-major
// upper triangle. Row i is a contiguous output segment:
//   base(i) = i*(n-1) - i*(i-1)/2, len = n-1-i, out[base+t] = a[i+1+t] - a[i]
// Pair rows (g, n-2-g): lengths sum to exactly n -> balanced work.
// Each block handles PPB consecutive pairs (PPB*n elements = 32KB @ n=1024).
// Stores are float4 STG.128 aligned to the OUTPUT (head/tail peel <=3 elems).

#define TPB 256
#define PPB 8

__global__ void __launch_bounds__(TPB)
relpos_kernel(const float* __restrict__ in, float* __restrict__ out,
              int n, int G, int chunks, long long P)
{
    int b = blockIdx.x / chunks;
    int c = blockIdx.x - b * chunks;
    const int tid = threadIdx.x;

    const float* __restrict__ arow = in + (long long)b * n;
    float* __restrict__ outb = out + (long long)b * P;

    int g0 = c * PPB;

    #pragma unroll
    for (int p = 0; p < PPB; ++p) {
        int g = g0 + p;
        if (g >= G) break;
        int i1 = g;
        int i2 = n - 2 - g;

        #pragma unroll
        for (int r = 0; r < 2; ++r) {
            int i = r ? i2 : i1;
            if (r && i2 <= i1) break;          // middle row: handle once

            long long base = (long long)i * (n - 1) - (long long)i * (i - 1) / 2;
            int len = n - 1 - i;
            float ai = __ldg(arow + i);
            const float* __restrict__ src = arow + i + 1;
            float*       __restrict__ dst = outb + base;

            // peel to 16B alignment of dst
            int head = (int)((4 - (base & 3)) & 3);
            if (head > len) head = len;
            if (tid < head) dst[tid] = src[tid] - ai;

            int rem  = len - head;
            int nvec = rem >> 2;
            const float* __restrict__ s2 = src + head;
            float4*      __restrict__ d2 = (float4*)(dst + head);

            // len <= n-1 < 4*TPB+head  =>  this loop runs at most once per thread
            for (int v = tid; v < nvec; v += TPB) {
                int e = v << 2;
                float4 o;
                o.x = s2[e + 0] - ai;
                o.y = s2[e + 1] - ai;
                o.z = s2[e + 2] - ai;
                o.w = s2[e + 3] - ai;
                __stcs(d2 + v, o);             // streaming STG.128
            }

            int tmod = rem & 3;
            if (tid < tmod) {
                int off = head + (nvec << 2) + tid;
                dst[off] = src[off] - ai;
            }
        }
    }
}

extern "C" void kernel_launch(void* const* d_in, const int* in_sizes, int n_in,
                              void* d_out, int out_size)
{
    const float* in = (const float*)d_in[0];
    float* out = (float*)d_out;

    long long total_in = in_sizes[0];                  // B * n
    int n = (int)(2LL * (long long)out_size / total_in + 1);
    int B = (int)(total_in / n);
    long long P = (long long)n * (n - 1) / 2;

    int G = (n + 1) / 2;                               // row-pair groups
    int chunks = (G + PPB - 1) / PPB;

    relpos_kernel<<<B * chunks, TPB>>>(in, out, n, G, chunks, P);
}

// round 3
// speedup vs baseline: 2.5931x; 2.3098x over previous
#include <cuda_runtime.h>

// RelativePosition: out[b, k(i,j)] = a[b,j] - a[b,i], j > i, row-major
// strict upper triangle. Row i = contiguous output segment:
//   base(i) = i*(n-1) - i*(i-1)/2, len = n-1-i, out[base+t] = a[i+1+t] - a[i]
//
// R3 design (kill the issue bottleneck):
//  * 4 shifted smem copies of the input row: sm[s][k] = a[k+s]. A source
//    window a[x..x+3] is an ALIGNED LDS.128 from copy (x&3) at word (x - x&3).
//  * one WARP per row (rows paired g <-> n-2-g for balance), so per-row
//    setup/peel is paid once per row, not once per block-warp.
//  * all-32-bit indexing (B*P = 67M < 2^31), incremental triangular bases.
//  * float4 streaming stores (__stcs), aligned to the output.

#define TPB 256
#define PW  2                 // pairs per warp
#define PPB (PW * (TPB / 32)) // pairs per block = 16
#define NMAX 1024

__device__ __forceinline__ void process_row(
    const float (*__restrict__ sm)[NMAX], float* __restrict__ outb,
    int n, int i, int base, int lid)
{
    int len  = n - 1 - i;
    float ai = sm[0][i];
    int src0 = i + 1;

    int head = (-base) & 3;
    if (head > len) head = len;
    if (lid < head) outb[base + lid] = sm[0][src0 + lid] - ai;

    int rem  = len - head;
    int nvec = rem >> 2;
    int x    = src0 + head;
    int sh   = x & 3;
    const float4* __restrict__ sp = (const float4*)(&sm[sh][x - sh]); // 16B aligned
    float4* __restrict__ dp = (float4*)(outb + base + head);          // 16B aligned

    #pragma unroll 4
    for (int v = lid; v < nvec; v += 32) {
        float4 q = sp[v];
        float4 o = make_float4(q.x - ai, q.y - ai, q.z - ai, q.w - ai);
        __stcs(dp + v, o);
    }

    int tm = rem & 3;
    if (lid < tm) {
        int t = head + (nvec << 2) + lid;
        outb[base + t] = sm[0][src0 + t] - ai;
    }
}

__global__ void __launch_bounds__(TPB)
relpos_kernel(const float* __restrict__ in, float* __restrict__ out,
              int n, int G, int chunks, int P)
{
    __shared__ float sm[4][NMAX];

    int b = blockIdx.x / chunks;
    int c = blockIdx.x - b * chunks;
    const int tid = threadIdx.x;
    const int wid = tid >> 5;
    const int lid = tid & 31;

    const float* __restrict__ arow = in + b * n;   // b*n small, 32-bit fine
    float* __restrict__ outb = out + b * P;        // b*P < 2^31

    // ---- fill 4 shifted copies of the input row ----
    for (int t = tid; t < (n >> 2); t += TPB) {
        float4 v = ((const float4*)arow)[t];
        float vv[4] = {v.x, v.y, v.z, v.w};
        int x0 = t << 2;
        #pragma unroll
        for (int s = 0; s < 4; ++s)
            #pragma unroll
            for (int cc = 0; cc < 4; ++cc) {
                int xx = x0 + cc;
                if (xx >= s) sm[s][xx - s] = vv[cc];
            }
    }
    __syncthreads();

    int gs = c * PPB + wid * PW;   // this warp's first pair index

    // ---- rows i1 = gs .. gs+PW-1 (consecutive -> incremental base) ----
    {
        int i = gs;
        int base = i * (n - 1) - ((i * (i - 1)) >> 1);
        #pragma unroll
        for (int p = 0; p < PW; ++p) {
            if (i < G) process_row(sm, outb, n, i, base, lid);
            base += n - 1 - i;
            ++i;
        }
    }
    // ---- rows i2 = n-2-gs, descending (incremental base) ----
    {
        int i2 = n - 2 - gs;
        int base2 = i2 * (n - 1) - ((i2 * (i2 - 1)) >> 1);
        #pragma unroll
        for (int p = 0; p < PW; ++p) {
            int g = gs + p;
            if (g < G && i2 > g) process_row(sm, outb, n, i2, base2, lid);
            base2 -= (n - i2);   // base(i2-1) = base(i2) - len(i2-1)
            --i2;
        }
    }
}

extern "C" void kernel_launch(void* const* d_in, const int* in_sizes, int n_in,
                              void* d_out, int out_size)
{
    const float* in = (const float*)d_in[0];
    float* out = (float*)d_out;

    long long total_in = in_sizes[0];                       // B * n
    int n = (int)(2LL * (long long)out_size / total_in + 1); // 1024
    int B = (int)(total_in / n);                             // 128
    int P = n * (n - 1) / 2;                                 // 523776 < 2^31

    int G = n / 2;                                           // pair groups (512)
    int chunks = (G + PPB - 1) / PPB;                        // 32

    relpos_kernel<<<B * chunks, TPB>>>(in, out, n, G, chunks, P);
}